// round 1
// baseline (speedup 1.0000x reference)
#include <cuda_runtime.h>
#include <math.h>

// Problem constants (fixed by the reference)
#define BATCH 4
#define PP 900
#define DM 512
#define HH 8
#define DK 64
#define SIDE 30
#define C1 32          // conv1 output channels (4*h)
#define P2 810000      // 900*900
#define MP (BATCH*PP)  // 3600

// ---------------- scratch (device globals; no runtime allocation) ----------
__device__ __align__(128) float g_q[MP * DM];          // Q projection [b,p,d]
__device__ __align__(128) float g_k[MP * DM];          // K projection [b,p,d]
__device__ __align__(128) float g_scores[BATCH * HH * P2]; // scores / attn (in-place)
__device__ __align__(128) int   g_idx[BATCH * HH * PP];    // column argmax
__device__ __align__(128) float g_c1[BATCH * C1 * P2];     // conv1 output

// ---------------- projection GEMM: C = A @ W^T + bias ----------------------
// A [3600,512] row-major, W [512,512] row-major (both K-contiguous)
// 64x64 tile, BK=16, 256 threads, 4x4 micro-tile
__global__ __launch_bounds__(256) void proj_gemm_kernel(
    const float* __restrict__ A, const float* __restrict__ Wm,
    const float* __restrict__ bias, int which)
{
    float* C = which ? g_k : g_q;
    __shared__ float As[16][65];
    __shared__ float Bs[16][65];
    const int t  = threadIdx.x;
    const int m0 = blockIdx.y * 64;
    const int n0 = blockIdx.x * 64;
    const int lr = t >> 2;
    const int lc = (t & 3) << 2;
    const int ty = t >> 4, tx = t & 15;
    float acc[4][4] = {};

    for (int k0 = 0; k0 < DM; k0 += 16) {
        int ar = m0 + lr;
        float4 av = make_float4(0.f, 0.f, 0.f, 0.f);
        if (ar < MP) av = *(const float4*)(A + (size_t)ar * DM + k0 + lc);
        float4 bv = *(const float4*)(Wm + (size_t)(n0 + lr) * DM + k0 + lc);
        if (k0) __syncthreads();
        As[lc + 0][lr] = av.x; As[lc + 1][lr] = av.y;
        As[lc + 2][lr] = av.z; As[lc + 3][lr] = av.w;
        Bs[lc + 0][lr] = bv.x; Bs[lc + 1][lr] = bv.y;
        Bs[lc + 2][lr] = bv.z; Bs[lc + 3][lr] = bv.w;
        __syncthreads();
        #pragma unroll
        for (int kk = 0; kk < 16; kk++) {
            float a0 = As[kk][ty*4+0], a1 = As[kk][ty*4+1];
            float a2 = As[kk][ty*4+2], a3 = As[kk][ty*4+3];
            float b0 = Bs[kk][tx*4+0], b1 = Bs[kk][tx*4+1];
            float b2 = Bs[kk][tx*4+2], b3 = Bs[kk][tx*4+3];
            acc[0][0] = fmaf(a0,b0,acc[0][0]); acc[0][1] = fmaf(a0,b1,acc[0][1]);
            acc[0][2] = fmaf(a0,b2,acc[0][2]); acc[0][3] = fmaf(a0,b3,acc[0][3]);
            acc[1][0] = fmaf(a1,b0,acc[1][0]); acc[1][1] = fmaf(a1,b1,acc[1][1]);
            acc[1][2] = fmaf(a1,b2,acc[1][2]); acc[1][3] = fmaf(a1,b3,acc[1][3]);
            acc[2][0] = fmaf(a2,b0,acc[2][0]); acc[2][1] = fmaf(a2,b1,acc[2][1]);
            acc[2][2] = fmaf(a2,b2,acc[2][2]); acc[2][3] = fmaf(a2,b3,acc[2][3]);
            acc[3][0] = fmaf(a3,b0,acc[3][0]); acc[3][1] = fmaf(a3,b1,acc[3][1]);
            acc[3][2] = fmaf(a3,b2,acc[3][2]); acc[3][3] = fmaf(a3,b3,acc[3][3]);
        }
    }
    #pragma unroll
    for (int i = 0; i < 4; i++) {
        int r = m0 + ty*4 + i;
        if (r >= MP) continue;
        #pragma unroll
        for (int j = 0; j < 4; j++) {
            int c = n0 + tx*4 + j;
            C[(size_t)r * DM + c] = acc[i][j] + bias[c];
        }
    }
}

// ---------------- batched scores GEMM: scores[b,h] = Qh @ Kh^T -------------
// per (b,h): A rows 900, K=64, lda=512 (slice of projection)
__global__ __launch_bounds__(256) void scores_gemm_kernel()
{
    const int z = blockIdx.z;
    const int b = z >> 3, h = z & 7;
    const float* A  = g_q + (size_t)b * PP * DM + h * DK;
    const float* Bm = g_k + (size_t)b * PP * DM + h * DK;
    float* C = g_scores + (size_t)z * P2;

    __shared__ float As[16][65];
    __shared__ float Bs[16][65];
    const int t  = threadIdx.x;
    const int m0 = blockIdx.y * 64;
    const int n0 = blockIdx.x * 64;
    const int lr = t >> 2;
    const int lc = (t & 3) << 2;
    const int ty = t >> 4, tx = t & 15;
    float acc[4][4] = {};

    for (int k0 = 0; k0 < DK; k0 += 16) {
        int ar = m0 + lr;
        int br = n0 + lr;
        float4 av = make_float4(0.f,0.f,0.f,0.f);
        float4 bv = make_float4(0.f,0.f,0.f,0.f);
        if (ar < PP) av = *(const float4*)(A  + (size_t)ar * DM + k0 + lc);
        if (br < PP) bv = *(const float4*)(Bm + (size_t)br * DM + k0 + lc);
        if (k0) __syncthreads();
        As[lc + 0][lr] = av.x; As[lc + 1][lr] = av.y;
        As[lc + 2][lr] = av.z; As[lc + 3][lr] = av.w;
        Bs[lc + 0][lr] = bv.x; Bs[lc + 1][lr] = bv.y;
        Bs[lc + 2][lr] = bv.z; Bs[lc + 3][lr] = bv.w;
        __syncthreads();
        #pragma unroll
        for (int kk = 0; kk < 16; kk++) {
            float a0 = As[kk][ty*4+0], a1 = As[kk][ty*4+1];
            float a2 = As[kk][ty*4+2], a3 = As[kk][ty*4+3];
            float b0 = Bs[kk][tx*4+0], b1 = Bs[kk][tx*4+1];
            float b2 = Bs[kk][tx*4+2], b3 = Bs[kk][tx*4+3];
            acc[0][0] = fmaf(a0,b0,acc[0][0]); acc[0][1] = fmaf(a0,b1,acc[0][1]);
            acc[0][2] = fmaf(a0,b2,acc[0][2]); acc[0][3] = fmaf(a0,b3,acc[0][3]);
            acc[1][0] = fmaf(a1,b0,acc[1][0]); acc[1][1] = fmaf(a1,b1,acc[1][1]);
            acc[1][2] = fmaf(a1,b2,acc[1][2]); acc[1][3] = fmaf(a1,b3,acc[1][3]);
            acc[2][0] = fmaf(a2,b0,acc[2][0]); acc[2][1] = fmaf(a2,b1,acc[2][1]);
            acc[2][2] = fmaf(a2,b2,acc[2][2]); acc[2][3] = fmaf(a2,b3,acc[2][3]);
            acc[3][0] = fmaf(a3,b0,acc[3][0]); acc[3][1] = fmaf(a3,b1,acc[3][1]);
            acc[3][2] = fmaf(a3,b2,acc[3][2]); acc[3][3] = fmaf(a3,b3,acc[3][3]);
        }
    }
    #pragma unroll
    for (int i = 0; i < 4; i++) {
        int r = m0 + ty*4 + i;
        if (r >= PP) continue;
        #pragma unroll
        for (int j = 0; j < 4; j++) {
            int c = n0 + tx*4 + j;
            if (c < PP) C[(size_t)r * PP + c] = acc[i][j];
        }
    }
}

// ---------------- column argmax over p for each (bh, w) --------------------
__global__ __launch_bounds__(256) void argmax_kernel()
{
    const int w  = blockIdx.x * 256 + threadIdx.x;
    const int bh = blockIdx.y;
    if (w >= PP) return;
    const float* base = g_scores + (size_t)bh * P2 + w;
    float best = base[0];
    int   bi = 0;
    int p = 1;
    for (; p + 3 < PP; p += 4) {
        float v0 = base[(size_t)(p+0) * PP];
        float v1 = base[(size_t)(p+1) * PP];
        float v2 = base[(size_t)(p+2) * PP];
        float v3 = base[(size_t)(p+3) * PP];
        if (v0 > best) { best = v0; bi = p + 0; }
        if (v1 > best) { best = v1; bi = p + 1; }
        if (v2 > best) { best = v2; bi = p + 2; }
        if (v3 > best) { best = v3; bi = p + 3; }
    }
    for (; p < PP; p++) {
        float v = base[(size_t)p * PP];
        if (v > best) { best = v; bi = p; }
    }
    g_idx[bh * PP + w] = bi;
}

// ---------------- gaussian modulation + scale + softmax (in-place) ---------
__global__ __launch_bounds__(256) void gauss_softmax_kernel()
{
    const int p  = blockIdx.x;
    const int bh = blockIdx.y;
    float* row = g_scores + ((size_t)bh * PP + p) * PP;
    const int* idxr = g_idx + bh * PP;
    const int t = threadIdx.x;
    const float ys0 = -1.0f + (2.0f / 29.0f) * (float)(p / SIDE);
    const float xs0 = -1.0f + (2.0f / 29.0f) * (float)(p % SIDE);

    __shared__ float sh[32];
    float v[4];
    float m = -3.0e38f;
    #pragma unroll
    for (int i = 0; i < 4; i++) {
        int w = t + i * 256;
        v[i] = -3.0e38f;
        if (w < PP) {
            int id = idxr[w];
            int iy = id / SIDE;
            float fy = (float)iy;
            float fx = (float)(id - iy * SIDE);
            float ddx = xs0 - fx;
            float ddy = ys0 - fy;
            float g = expf(-(ddx * ddx + ddy * ddy) * (1.0f / 50.0f));
            v[i] = g * row[w] * 0.125f;
            m = fmaxf(m, v[i]);
        }
    }
    // block max
    #pragma unroll
    for (int off = 16; off; off >>= 1) m = fmaxf(m, __shfl_xor_sync(0xffffffffu, m, off));
    if ((t & 31) == 0) sh[t >> 5] = m;
    __syncthreads();
    if (t < 32) {
        float x = (t < 8) ? sh[t] : -3.0e38f;
        #pragma unroll
        for (int off = 4; off; off >>= 1) x = fmaxf(x, __shfl_xor_sync(0xffffffffu, x, off));
        if (t == 0) sh[0] = x;
    }
    __syncthreads();
    m = sh[0];
    __syncthreads();

    float e[4];
    float s = 0.f;
    #pragma unroll
    for (int i = 0; i < 4; i++) {
        int w = t + i * 256;
        e[i] = 0.f;
        if (w < PP) { e[i] = expf(v[i] - m); s += e[i]; }
    }
    #pragma unroll
    for (int off = 16; off; off >>= 1) s += __shfl_xor_sync(0xffffffffu, s, off);
    if ((t & 31) == 0) sh[t >> 5] = s;
    __syncthreads();
    if (t < 32) {
        float x = (t < 8) ? sh[t] : 0.f;
        #pragma unroll
        for (int off = 4; off; off >>= 1) x += __shfl_xor_sync(0xffffffffu, x, off);
        if (t == 0) sh[0] = x;
    }
    __syncthreads();
    float inv = 1.0f / sh[0];
    #pragma unroll
    for (int i = 0; i < 4; i++) {
        int w = t + i * 256;
        if (w < PP) row[w] = e[i] * inv;
    }
}

// ---------------- conv1 (8->32 ch, 3x3 SAME) + bias + relu -----------------
// block = (p, b). Each thread: 8 output channels x 4 w-positions.
__global__ __launch_bounds__(256) void conv1_kernel(
    const float* __restrict__ w1, const float* __restrict__ b1)
{
    const int p = blockIdx.x;
    const int b = blockIdx.y;
    __shared__ float wsm[C1 * 8 * 9];  // [oc][ci][dy][dx]
    for (int i = threadIdx.x; i < C1 * 8 * 9; i += 256) wsm[i] = w1[i];
    __syncthreads();

    const int ocg  = threadIdx.x >> 6;  // 0..3 -> oc base = ocg*8
    const int slot = threadIdx.x & 63;
    const float* inb = g_scores + (size_t)b * HH * P2;

    float bia[8];
    #pragma unroll
    for (int o = 0; o < 8; o++) bia[o] = b1[ocg * 8 + o];

    #pragma unroll 1
    for (int j = 0; j < 4; j++) {
        const int w0 = slot + 256 * j;   // w = w0 + 64*k, k=0..3
        float acc[4][8];
        #pragma unroll
        for (int k = 0; k < 4; k++)
            #pragma unroll
            for (int o = 0; o < 8; o++) acc[k][o] = bia[o];

        #pragma unroll 1
        for (int ci = 0; ci < 8; ci++) {
            #pragma unroll
            for (int dy = 0; dy < 3; dy++) {
                int r = p + dy - 1;
                if (r < 0 || r >= PP) continue;
                const float* rowp = inb + ((size_t)ci * PP + r) * PP;
                #pragma unroll
                for (int dx = 0; dx < 3; dx++) {
                    float wr[8];
                    #pragma unroll
                    for (int o = 0; o < 8; o++)
                        wr[o] = wsm[((ocg * 8 + o) * 8 + ci) * 9 + dy * 3 + dx];
                    #pragma unroll
                    for (int k = 0; k < 4; k++) {
                        int x = w0 + 64 * k + dx - 1;
                        float vv = (x >= 0 && x < PP) ? rowp[x] : 0.f;
                        #pragma unroll
                        for (int o = 0; o < 8; o++)
                            acc[k][o] = fmaf(vv, wr[o], acc[k][o]);
                    }
                }
            }
        }
        size_t outb = (((size_t)b * C1 + ocg * 8) * PP + p) * (size_t)PP;
        #pragma unroll
        for (int k = 0; k < 4; k++) {
            int w = w0 + 64 * k;
            if (w < PP) {
                #pragma unroll
                for (int o = 0; o < 8; o++)
                    g_c1[outb + (size_t)o * P2 + w] = fmaxf(acc[k][o], 0.f);
            }
        }
    }
}

// ------- conv2 (32->8 ch) + bias + relu + value-dot + head-mean ------------
// block = (p, b); each thread: all 8 oc x 4 w; block-reduce to out[b,p]
__global__ __launch_bounds__(256) void conv2_reduce_kernel(
    const float* __restrict__ w2, const float* __restrict__ b2,
    const float* __restrict__ value, float* __restrict__ out)
{
    const int p = blockIdx.x;
    const int b = blockIdx.y;
    __shared__ float wsm[8 * C1 * 9];  // [oc][ci][dy][dx]
    for (int i = threadIdx.x; i < 8 * C1 * 9; i += 256) wsm[i] = w2[i];
    __syncthreads();

    const int t = threadIdx.x;
    const float* inb = g_c1 + (size_t)b * C1 * P2;

    float acc[4][8];
    #pragma unroll
    for (int k = 0; k < 4; k++)
        #pragma unroll
        for (int o = 0; o < 8; o++) acc[k][o] = b2[o];

    #pragma unroll 1
    for (int ci = 0; ci < C1; ci++) {
        #pragma unroll
        for (int dy = 0; dy < 3; dy++) {
            int r = p + dy - 1;
            if (r < 0 || r >= PP) continue;
            const float* rowp = inb + ((size_t)ci * PP + r) * PP;
            #pragma unroll
            for (int dx = 0; dx < 3; dx++) {
                float wr[8];
                #pragma unroll
                for (int o = 0; o < 8; o++)
                    wr[o] = wsm[(o * C1 + ci) * 9 + dy * 3 + dx];
                #pragma unroll
                for (int k = 0; k < 4; k++) {
                    int x = t + 256 * k + dx - 1;
                    float vv = (x >= 0 && x < PP) ? rowp[x] : 0.f;
                    #pragma unroll
                    for (int o = 0; o < 8; o++)
                        acc[k][o] = fmaf(vv, wr[o], acc[k][o]);
                }
            }
        }
    }

    float part = 0.f;
    #pragma unroll
    for (int k = 0; k < 4; k++) {
        int w = t + 256 * k;
        if (w < PP) {
            float val = value[b * PP + w];
            float s = 0.f;
            #pragma unroll
            for (int o = 0; o < 8; o++) s += fmaxf(acc[k][o], 0.f);
            part += s * val;
        }
    }
    __shared__ float sh[32];
    #pragma unroll
    for (int off = 16; off; off >>= 1) part += __shfl_xor_sync(0xffffffffu, part, off);
    if ((t & 31) == 0) sh[t >> 5] = part;
    __syncthreads();
    if (t < 32) {
        float x = (t < 8) ? sh[t] : 0.f;
        #pragma unroll
        for (int off = 4; off; off >>= 1) x += __shfl_xor_sync(0xffffffffu, x, off);
        if (t == 0) out[b * PP + p] = x * 0.125f;  // mean over 8 heads
    }
}

// ---------------------------------------------------------------------------
extern "C" void kernel_launch(void* const* d_in, const int* in_sizes, int n_in,
                              void* d_out, int out_size)
{
    const float* query = (const float*)d_in[0];
    const float* key_t = (const float*)d_in[1];
    const float* value = (const float*)d_in[2];
    const float* Wq    = (const float*)d_in[3];
    const float* bq    = (const float*)d_in[4];
    const float* Wk    = (const float*)d_in[5];
    const float* bk    = (const float*)d_in[6];
    const float* c1w   = (const float*)d_in[7];
    const float* c1b   = (const float*)d_in[8];
    const float* c2w   = (const float*)d_in[9];
    const float* c2b   = (const float*)d_in[10];
    float* out = (float*)d_out;
    (void)in_sizes; (void)n_in; (void)out_size;

    // 1) projections
    proj_gemm_kernel<<<dim3(8, 57), 256>>>(query, Wq, bq, 0);
    proj_gemm_kernel<<<dim3(8, 57), 256>>>(key_t, Wk, bk, 1);
    // 2) batched scores
    scores_gemm_kernel<<<dim3(15, 15, 32), 256>>>();
    // 3) column argmax (pre-modulation scores)
    argmax_kernel<<<dim3(4, 32), 256>>>();
    // 4) gaussian modulation + scale + softmax (in-place)
    gauss_softmax_kernel<<<dim3(900, 32), 256>>>();
    // 5) conv1 + relu
    conv1_kernel<<<dim3(900, 4), 256>>>(c1w, c1b);
    // 6) conv2 + relu + value-dot + head-mean
    conv2_reduce_kernel<<<dim3(900, 4), 256>>>(c2w, c2b, value, out);
}

// round 2
// speedup vs baseline: 1.1531x; 1.1531x over previous
#include <cuda_runtime.h>
#include <math.h>

// Problem constants (fixed by the reference)
#define BATCH 4
#define PP 900
#define DM 512
#define HH 8
#define DK 64
#define SIDE 30
#define C1 32          // conv1 output channels (4*h)
#define P2 810000      // 900*900
#define MP (BATCH*PP)  // 3600

typedef unsigned long long u64;

// ---------------- packed f32x2 helpers -------------------------------------
__device__ __forceinline__ u64 pack2(float a, float b) {
    u64 r; asm("mov.b64 %0, {%1,%2};" : "=l"(r) : "f"(a), "f"(b)); return r;
}
__device__ __forceinline__ u64 ffma2(u64 a, u64 b, u64 c) {
    u64 d; asm("fma.rn.f32x2 %0, %1, %2, %3;" : "=l"(d) : "l"(a), "l"(b), "l"(c)); return d;
}
__device__ __forceinline__ float2 unpack2(u64 v) {
    float2 f; asm("mov.b64 {%0,%1}, %2;" : "=f"(f.x), "=f"(f.y) : "l"(v)); return f;
}

// ---------------- scratch (device globals; no runtime allocation) ----------
__device__ __align__(128) float g_q[MP * DM];              // Q projection [b,p,d]
__device__ __align__(128) float g_k[MP * DM];              // K projection [b,p,d]
__device__ __align__(128) float g_scores[BATCH * HH * P2]; // scores / attn (in-place)
__device__ __align__(128) int   g_idx[BATCH * HH * PP];    // column argmax
__device__ __align__(128) float g_c1[BATCH * C1 * P2];     // conv1 output

// ---------------- projection GEMM: C = A @ W^T + bias ----------------------
// A [3600,512] row-major, W [512,512] row-major (both K-contiguous)
// 64x64 tile, BK=16, 256 threads, 4x4 micro-tile; acc packed over columns
__global__ __launch_bounds__(256) void proj_gemm_kernel(
    const float* __restrict__ A, const float* __restrict__ Wm,
    const float* __restrict__ bias, int which)
{
    float* C = which ? g_k : g_q;
    __shared__ __align__(16) float As[16][66];
    __shared__ __align__(16) float Bs[16][66];
    const int t  = threadIdx.x;
    const int m0 = blockIdx.y * 64;
    const int n0 = blockIdx.x * 64;
    const int lr = t >> 2;
    const int lc = (t & 3) << 2;
    const int ty = t >> 4, tx = t & 15;
    u64 acc[4][2];
    #pragma unroll
    for (int i = 0; i < 4; i++) { acc[i][0] = 0ull; acc[i][1] = 0ull; }

    for (int k0 = 0; k0 < DM; k0 += 16) {
        int ar = m0 + lr;
        float4 av = make_float4(0.f, 0.f, 0.f, 0.f);
        if (ar < MP) av = *(const float4*)(A + (size_t)ar * DM + k0 + lc);
        float4 bv = *(const float4*)(Wm + (size_t)(n0 + lr) * DM + k0 + lc);
        if (k0) __syncthreads();
        As[lc + 0][lr] = av.x; As[lc + 1][lr] = av.y;
        As[lc + 2][lr] = av.z; As[lc + 3][lr] = av.w;
        Bs[lc + 0][lr] = bv.x; Bs[lc + 1][lr] = bv.y;
        Bs[lc + 2][lr] = bv.z; Bs[lc + 3][lr] = bv.w;
        __syncthreads();
        #pragma unroll
        for (int kk = 0; kk < 16; kk++) {
            u64 b01 = *(const u64*)&Bs[kk][tx * 4];
            u64 b23 = *(const u64*)&Bs[kk][tx * 4 + 2];
            #pragma unroll
            for (int i = 0; i < 4; i++) {
                float a = As[kk][ty * 4 + i];
                u64 aa = pack2(a, a);
                acc[i][0] = ffma2(aa, b01, acc[i][0]);
                acc[i][1] = ffma2(aa, b23, acc[i][1]);
            }
        }
    }
    #pragma unroll
    for (int i = 0; i < 4; i++) {
        int r = m0 + ty * 4 + i;
        if (r >= MP) continue;
        int c = n0 + tx * 4;
        float2 f01 = unpack2(acc[i][0]);
        float2 f23 = unpack2(acc[i][1]);
        C[(size_t)r * DM + c + 0] = f01.x + bias[c + 0];
        C[(size_t)r * DM + c + 1] = f01.y + bias[c + 1];
        C[(size_t)r * DM + c + 2] = f23.x + bias[c + 2];
        C[(size_t)r * DM + c + 3] = f23.y + bias[c + 3];
    }
}

// ---------------- batched scores GEMM: scores[b,h] = Qh @ Kh^T -------------
__global__ __launch_bounds__(256) void scores_gemm_kernel()
{
    const int z = blockIdx.z;
    const int b = z >> 3, h = z & 7;
    const float* A  = g_q + (size_t)b * PP * DM + h * DK;
    const float* Bm = g_k + (size_t)b * PP * DM + h * DK;
    float* C = g_scores + (size_t)z * P2;

    __shared__ __align__(16) float As[16][66];
    __shared__ __align__(16) float Bs[16][66];
    const int t  = threadIdx.x;
    const int m0 = blockIdx.y * 64;
    const int n0 = blockIdx.x * 64;
    const int lr = t >> 2;
    const int lc = (t & 3) << 2;
    const int ty = t >> 4, tx = t & 15;
    u64 acc[4][2];
    #pragma unroll
    for (int i = 0; i < 4; i++) { acc[i][0] = 0ull; acc[i][1] = 0ull; }

    for (int k0 = 0; k0 < DK; k0 += 16) {
        int ar = m0 + lr;
        int br = n0 + lr;
        float4 av = make_float4(0.f, 0.f, 0.f, 0.f);
        float4 bv = make_float4(0.f, 0.f, 0.f, 0.f);
        if (ar < PP) av = *(const float4*)(A  + (size_t)ar * DM + k0 + lc);
        if (br < PP) bv = *(const float4*)(Bm + (size_t)br * DM + k0 + lc);
        if (k0) __syncthreads();
        As[lc + 0][lr] = av.x; As[lc + 1][lr] = av.y;
        As[lc + 2][lr] = av.z; As[lc + 3][lr] = av.w;
        Bs[lc + 0][lr] = bv.x; Bs[lc + 1][lr] = bv.y;
        Bs[lc + 2][lr] = bv.z; Bs[lc + 3][lr] = bv.w;
        __syncthreads();
        #pragma unroll
        for (int kk = 0; kk < 16; kk++) {
            u64 b01 = *(const u64*)&Bs[kk][tx * 4];
            u64 b23 = *(const u64*)&Bs[kk][tx * 4 + 2];
            #pragma unroll
            for (int i = 0; i < 4; i++) {
                float a = As[kk][ty * 4 + i];
                u64 aa = pack2(a, a);
                acc[i][0] = ffma2(aa, b01, acc[i][0]);
                acc[i][1] = ffma2(aa, b23, acc[i][1]);
            }
        }
    }
    #pragma unroll
    for (int i = 0; i < 4; i++) {
        int r = m0 + ty * 4 + i;
        if (r >= PP) continue;
        int c = n0 + tx * 4;
        float2 f01 = unpack2(acc[i][0]);
        float2 f23 = unpack2(acc[i][1]);
        if (c + 0 < PP) C[(size_t)r * PP + c + 0] = f01.x;
        if (c + 1 < PP) C[(size_t)r * PP + c + 1] = f01.y;
        if (c + 2 < PP) C[(size_t)r * PP + c + 2] = f23.x;
        if (c + 3 < PP) C[(size_t)r * PP + c + 3] = f23.y;
    }
}

// ---------------- column argmax over p for each (bh, w) --------------------
__global__ __launch_bounds__(256) void argmax_kernel()
{
    const int w  = blockIdx.x * 256 + threadIdx.x;
    const int bh = blockIdx.y;
    if (w >= PP) return;
    const float* base = g_scores + (size_t)bh * P2 + w;
    float best = base[0];
    int   bi = 0;
    int p = 1;
    for (; p + 7 < PP; p += 8) {
        float v[8];
        #pragma unroll
        for (int u = 0; u < 8; u++) v[u] = base[(size_t)(p + u) * PP];
        #pragma unroll
        for (int u = 0; u < 8; u++)
            if (v[u] > best) { best = v[u]; bi = p + u; }
    }
    for (; p < PP; p++) {
        float v = base[(size_t)p * PP];
        if (v > best) { best = v; bi = p; }
    }
    g_idx[bh * PP + w] = bi;
}

// ---------------- gaussian modulation + scale + softmax (in-place) ---------
__global__ __launch_bounds__(256) void gauss_softmax_kernel()
{
    const int p  = blockIdx.x;
    const int bh = blockIdx.y;
    float* row = g_scores + ((size_t)bh * PP + p) * PP;
    const int* idxr = g_idx + bh * PP;
    const int t = threadIdx.x;
    const float ys0 = -1.0f + (2.0f / 29.0f) * (float)(p / SIDE);
    const float xs0 = -1.0f + (2.0f / 29.0f) * (float)(p % SIDE);

    __shared__ float sh[32];
    float v[4];
    float m = -3.0e38f;
    #pragma unroll
    for (int i = 0; i < 4; i++) {
        int w = t + i * 256;
        v[i] = -3.0e38f;
        if (w < PP) {
            int id = idxr[w];
            int iy = id / SIDE;
            float fy = (float)iy;
            float fx = (float)(id - iy * SIDE);
            float ddx = xs0 - fx;
            float ddy = ys0 - fy;
            float g = expf(-(ddx * ddx + ddy * ddy) * (1.0f / 50.0f));
            v[i] = g * row[w] * 0.125f;
            m = fmaxf(m, v[i]);
        }
    }
    #pragma unroll
    for (int off = 16; off; off >>= 1) m = fmaxf(m, __shfl_xor_sync(0xffffffffu, m, off));
    if ((t & 31) == 0) sh[t >> 5] = m;
    __syncthreads();
    if (t < 32) {
        float x = (t < 8) ? sh[t] : -3.0e38f;
        #pragma unroll
        for (int off = 4; off; off >>= 1) x = fmaxf(x, __shfl_xor_sync(0xffffffffu, x, off));
        if (t == 0) sh[0] = x;
    }
    __syncthreads();
    m = sh[0];
    __syncthreads();

    float e[4];
    float s = 0.f;
    #pragma unroll
    for (int i = 0; i < 4; i++) {
        int w = t + i * 256;
        e[i] = 0.f;
        if (w < PP) { e[i] = expf(v[i] - m); s += e[i]; }
    }
    #pragma unroll
    for (int off = 16; off; off >>= 1) s += __shfl_xor_sync(0xffffffffu, s, off);
    if ((t & 31) == 0) sh[t >> 5] = s;
    __syncthreads();
    if (t < 32) {
        float x = (t < 8) ? sh[t] : 0.f;
        #pragma unroll
        for (int off = 4; off; off >>= 1) x += __shfl_xor_sync(0xffffffffu, x, off);
        if (t == 0) sh[0] = x;
    }
    __syncthreads();
    float inv = 1.0f / sh[0];
    #pragma unroll
    for (int i = 0; i < 4; i++) {
        int w = t + i * 256;
        if (w < PP) row[w] = e[i] * inv;
    }
}

// ---------------- conv1 (8->32 ch, 3x3 SAME) + bias + relu -----------------
// block = (p, b). Thread: 4 oc-pairs (8 channels) x 4 w-positions, packed f32x2.
__global__ __launch_bounds__(256) void conv1_kernel(
    const float* __restrict__ w1, const float* __restrict__ b1)
{
    const int p = blockIdx.x;
    const int b = blockIdx.y;
    // wsm[(ci*9 + dy*3 + dx)*16 + ocg*4 + op] = pack(w[oc0], w[oc0+1]), oc0 = ocg*8+op*2
    __shared__ u64 wsm[8 * 9 * 16];
    for (int i = threadIdx.x; i < 8 * 9 * 16; i += 256) {
        int op  = i & 3;
        int ocg = (i >> 2) & 3;
        int rest = i >> 4;                  // ci*9 + dydx
        int ci  = rest / 9;
        int dydx = rest - ci * 9;
        int oc0 = ocg * 8 + op * 2;
        float wa = w1[(oc0 * 8 + ci) * 9 + dydx];
        float wb = w1[((oc0 + 1) * 8 + ci) * 9 + dydx];
        wsm[i] = pack2(wa, wb);
    }
    __syncthreads();

    const int ocg  = threadIdx.x >> 6;  // 0..3 -> oc base = ocg*8
    const int slot = threadIdx.x & 63;
    const float* inb = g_scores + (size_t)b * HH * P2;

    u64 bia[4];
    #pragma unroll
    for (int op = 0; op < 4; op++)
        bia[op] = pack2(b1[ocg * 8 + op * 2], b1[ocg * 8 + op * 2 + 1]);

    #pragma unroll 1
    for (int j = 0; j < 4; j++) {
        const int w0 = slot + 256 * j;   // w = w0 + 64*k, k=0..3
        u64 acc[4][4];
        #pragma unroll
        for (int k = 0; k < 4; k++)
            #pragma unroll
            for (int op = 0; op < 4; op++) acc[k][op] = bia[op];

        #pragma unroll 1
        for (int ci = 0; ci < 8; ci++) {
            #pragma unroll
            for (int dy = 0; dy < 3; dy++) {
                int r = p + dy - 1;
                if (r < 0 || r >= PP) continue;
                const float* rowp = inb + ((size_t)ci * PP + r) * PP;
                u64 vm2[4], v02[4], vp2[4];
                #pragma unroll
                for (int k = 0; k < 4; k++) {
                    int x0 = w0 + 64 * k;
                    float vm = (x0 >= 1    && x0 - 1 < PP) ? rowp[x0 - 1] : 0.f;
                    float vc = (x0 < PP)                   ? rowp[x0]     : 0.f;
                    float vp = (x0 + 1 < PP)               ? rowp[x0 + 1] : 0.f;
                    vm2[k] = pack2(vm, vm);
                    v02[k] = pack2(vc, vc);
                    vp2[k] = pack2(vp, vp);
                }
                const u64* wbase = &wsm[(ci * 9 + dy * 3) * 16 + ocg * 4];
                #pragma unroll
                for (int dx = 0; dx < 3; dx++) {
                    u64 wp0 = wbase[dx * 16 + 0];
                    u64 wp1 = wbase[dx * 16 + 1];
                    u64 wp2 = wbase[dx * 16 + 2];
                    u64 wp3 = wbase[dx * 16 + 3];
                    const u64* vv = (dx == 0) ? vm2 : ((dx == 1) ? v02 : vp2);
                    #pragma unroll
                    for (int k = 0; k < 4; k++) {
                        acc[k][0] = ffma2(vv[k], wp0, acc[k][0]);
                        acc[k][1] = ffma2(vv[k], wp1, acc[k][1]);
                        acc[k][2] = ffma2(vv[k], wp2, acc[k][2]);
                        acc[k][3] = ffma2(vv[k], wp3, acc[k][3]);
                    }
                }
            }
        }
        size_t outb = (((size_t)b * C1 + ocg * 8) * PP + p) * (size_t)PP;
        #pragma unroll
        for (int k = 0; k < 4; k++) {
            int w = w0 + 64 * k;
            if (w < PP) {
                #pragma unroll
                for (int op = 0; op < 4; op++) {
                    float2 f = unpack2(acc[k][op]);
                    g_c1[outb + (size_t)(op * 2 + 0) * P2 + w] = fmaxf(f.x, 0.f);
                    g_c1[outb + (size_t)(op * 2 + 1) * P2 + w] = fmaxf(f.y, 0.f);
                }
            }
        }
    }
}

// ------- conv2 (32->8 ch) + bias + relu + value-dot + head-mean ------------
// block = (p, b); thread: 4 oc-pairs (8 ch) x 4 w; packed f32x2; block-reduce.
__global__ __launch_bounds__(256) void conv2_reduce_kernel(
    const float* __restrict__ w2, const float* __restrict__ b2,
    const float* __restrict__ value, float* __restrict__ out)
{
    const int p = blockIdx.x;
    const int b = blockIdx.y;
    // wsm[(ci*9 + dydx)*4 + op] = pack(w2[op*2], w2[op*2+1])
    __shared__ u64 wsm[32 * 9 * 4];
    for (int i = threadIdx.x; i < 32 * 9 * 4; i += 256) {
        int op = i & 3;
        int rest = i >> 2;                  // ci*9 + dydx
        int ci = rest / 9;
        int dydx = rest - ci * 9;
        int oc0 = op * 2;
        float wa = w2[(oc0 * 32 + ci) * 9 + dydx];
        float wb = w2[((oc0 + 1) * 32 + ci) * 9 + dydx];
        wsm[i] = pack2(wa, wb);
    }
    __syncthreads();

    const int t = threadIdx.x;
    const float* inb = g_c1 + (size_t)b * C1 * P2;

    u64 acc[4][4];
    #pragma unroll
    for (int k = 0; k < 4; k++)
        #pragma unroll
        for (int op = 0; op < 4; op++)
            acc[k][op] = pack2(b2[op * 2], b2[op * 2 + 1]);

    #pragma unroll 1
    for (int ci = 0; ci < C1; ci++) {
        #pragma unroll
        for (int dy = 0; dy < 3; dy++) {
            int r = p + dy - 1;
            if (r < 0 || r >= PP) continue;
            const float* rowp = inb + ((size_t)ci * PP + r) * PP;
            u64 vm2[4], v02[4], vp2[4];
            #pragma unroll
            for (int k = 0; k < 4; k++) {
                int x0 = t + 256 * k;
                float vm = (x0 >= 1    && x0 - 1 < PP) ? rowp[x0 - 1] : 0.f;
                float vc = (x0 < PP)                   ? rowp[x0]     : 0.f;
                float vp = (x0 + 1 < PP)               ? rowp[x0 + 1] : 0.f;
                vm2[k] = pack2(vm, vm);
                v02[k] = pack2(vc, vc);
                vp2[k] = pack2(vp, vp);
            }
            const u64* wbase = &wsm[(ci * 9 + dy * 3) * 4];
            #pragma unroll
            for (int dx = 0; dx < 3; dx++) {
                u64 wp0 = wbase[dx * 4 + 0];
                u64 wp1 = wbase[dx * 4 + 1];
                u64 wp2 = wbase[dx * 4 + 2];
                u64 wp3 = wbase[dx * 4 + 3];
                const u64* vv = (dx == 0) ? vm2 : ((dx == 1) ? v02 : vp2);
                #pragma unroll
                for (int k = 0; k < 4; k++) {
                    acc[k][0] = ffma2(vv[k], wp0, acc[k][0]);
                    acc[k][1] = ffma2(vv[k], wp1, acc[k][1]);
                    acc[k][2] = ffma2(vv[k], wp2, acc[k][2]);
                    acc[k][3] = ffma2(vv[k], wp3, acc[k][3]);
                }
            }
        }
    }

    float part = 0.f;
    #pragma unroll
    for (int k = 0; k < 4; k++) {
        int w = t + 256 * k;
        if (w < PP) {
            float val = value[b * PP + w];
            float s = 0.f;
            #pragma unroll
            for (int op = 0; op < 4; op++) {
                float2 f = unpack2(acc[k][op]);
                s += fmaxf(f.x, 0.f) + fmaxf(f.y, 0.f);
            }
            part += s * val;
        }
    }
    __shared__ float sh[32];
    #pragma unroll
    for (int off = 16; off; off >>= 1) part += __shfl_xor_sync(0xffffffffu, part, off);
    if ((t & 31) == 0) sh[t >> 5] = part;
    __syncthreads();
    if (t < 32) {
        float x = (t < 8) ? sh[t] : 0.f;
        #pragma unroll
        for (int off = 4; off; off >>= 1) x += __shfl_xor_sync(0xffffffffu, x, off);
        if (t == 0) out[b * PP + p] = x * 0.125f;  // mean over 8 heads
    }
}

// ---------------------------------------------------------------------------
extern "C" void kernel_launch(void* const* d_in, const int* in_sizes, int n_in,
                              void* d_out, int out_size)
{
    const float* query = (const float*)d_in[0];
    const float* key_t = (const float*)d_in[1];
    const float* value = (const float*)d_in[2];
    const float* Wq    = (const float*)d_in[3];
    const float* bq    = (const float*)d_in[4];
    const float* Wk    = (const float*)d_in[5];
    const float* bk    = (const float*)d_in[6];
    const float* c1w   = (const float*)d_in[7];
    const float* c1b   = (const float*)d_in[8];
    const float* c2w   = (const float*)d_in[9];
    const float* c2b   = (const float*)d_in[10];
    float* out = (float*)d_out;
    (void)in_sizes; (void)n_in; (void)out_size;

    // 1) projections
    proj_gemm_kernel<<<dim3(8, 57), 256>>>(query, Wq, bq, 0);
    proj_gemm_kernel<<<dim3(8, 57), 256>>>(key_t, Wk, bk, 1);
    // 2) batched scores
    scores_gemm_kernel<<<dim3(15, 15, 32), 256>>>();
    // 3) column argmax (pre-modulation scores)
    argmax_kernel<<<dim3(4, 32), 256>>>();
    // 4) gaussian modulation + scale + softmax (in-place)
    gauss_softmax_kernel<<<dim3(900, 32), 256>>>();
    // 5) conv1 + relu (f32x2 packed)
    conv1_kernel<<<dim3(900, 4), 256>>>(c1w, c1b);
    // 6) conv2 + relu + value-dot + head-mean (f32x2 packed)
    conv2_reduce_kernel<<<dim3(900, 4), 256>>>(c2w, c2b, value, out);
}

// round 3
// speedup vs baseline: 1.2913x; 1.1198x over previous
#include <cuda_runtime.h>
#include <math.h>

#define BATCH 4
#define PP 900
#define DM 512
#define HH 8
#define DK 64
#define SIDE 30
#define C1 32
#define P2 810000
#define MP (BATCH*PP)

typedef unsigned long long u64;

__device__ __forceinline__ u64 pack2(float a, float b) {
    u64 r; asm("mov.b64 %0, {%1,%2};" : "=l"(r) : "f"(a), "f"(b)); return r;
}
__device__ __forceinline__ u64 ffma2(u64 a, u64 b, u64 c) {
    u64 d; asm("fma.rn.f32x2 %0, %1, %2, %3;" : "=l"(d) : "l"(a), "l"(b), "l"(c)); return d;
}
__device__ __forceinline__ float2 unpack2(u64 v) {
    float2 f; asm("mov.b64 {%0,%1}, %2;" : "=f"(f.x), "=f"(f.y) : "l"(v)); return f;
}

__device__ __align__(128) float g_q[MP * DM];
__device__ __align__(128) float g_k[MP * DM];
__device__ __align__(128) float g_scores[BATCH * HH * P2];
__device__ __align__(128) int   g_idx[BATCH * HH * PP];
__device__ __align__(128) float g_c1[BATCH * C1 * P2];

// ---------------- projection GEMM: C = A @ W^T + bias ----------------------
// 128x128 tile, BK=16, 256 threads, 8x8 micro-tile (f32x2 packed over cols)
__global__ __launch_bounds__(256) void proj_gemm_kernel(
    const float* __restrict__ A, const float* __restrict__ Wm,
    const float* __restrict__ bias, int which)
{
    float* C = which ? g_k : g_q;
    __shared__ __align__(16) float As[16][132];
    __shared__ __align__(16) float Bs[16][132];
    const int t  = threadIdx.x;
    const int m0 = blockIdx.y * 128;
    const int n0 = blockIdx.x * 128;
    const int lr = t >> 2;
    const int lc = (t & 3) << 2;
    const int ty = t >> 4, tx = t & 15;
    u64 acc[8][4];
    #pragma unroll
    for (int i = 0; i < 8; i++)
        #pragma unroll
        for (int j = 0; j < 4; j++) acc[i][j] = 0ull;

    for (int k0 = 0; k0 < DM; k0 += 16) {
        int ar0 = m0 + lr, ar1 = m0 + lr + 64;
        float4 a0 = make_float4(0.f,0.f,0.f,0.f), a1 = a0;
        if (ar0 < MP) a0 = *(const float4*)(A + (size_t)ar0 * DM + k0 + lc);
        if (ar1 < MP) a1 = *(const float4*)(A + (size_t)ar1 * DM + k0 + lc);
        float4 b0 = *(const float4*)(Wm + (size_t)(n0 + lr)      * DM + k0 + lc);
        float4 b1 = *(const float4*)(Wm + (size_t)(n0 + lr + 64) * DM + k0 + lc);
        if (k0) __syncthreads();
        As[lc+0][lr] = a0.x; As[lc+1][lr] = a0.y; As[lc+2][lr] = a0.z; As[lc+3][lr] = a0.w;
        As[lc+0][lr+64] = a1.x; As[lc+1][lr+64] = a1.y; As[lc+2][lr+64] = a1.z; As[lc+3][lr+64] = a1.w;
        Bs[lc+0][lr] = b0.x; Bs[lc+1][lr] = b0.y; Bs[lc+2][lr] = b0.z; Bs[lc+3][lr] = b0.w;
        Bs[lc+0][lr+64] = b1.x; Bs[lc+1][lr+64] = b1.y; Bs[lc+2][lr+64] = b1.z; Bs[lc+3][lr+64] = b1.w;
        __syncthreads();
        #pragma unroll
        for (int kk = 0; kk < 16; kk++) {
            float a[8];
            *(float4*)&a[0] = *(const float4*)&As[kk][ty*8];
            *(float4*)&a[4] = *(const float4*)&As[kk][ty*8+4];
            ulonglong2 B0 = *(const ulonglong2*)&Bs[kk][tx*8];
            ulonglong2 B1 = *(const ulonglong2*)&Bs[kk][tx*8+4];
            #pragma unroll
            for (int i = 0; i < 8; i++) {
                u64 aa = pack2(a[i], a[i]);
                acc[i][0] = ffma2(aa, B0.x, acc[i][0]);
                acc[i][1] = ffma2(aa, B0.y, acc[i][1]);
                acc[i][2] = ffma2(aa, B1.x, acc[i][2]);
                acc[i][3] = ffma2(aa, B1.y, acc[i][3]);
            }
        }
    }
    const int c0 = n0 + tx * 8;
    float bi[8];
    #pragma unroll
    for (int j = 0; j < 8; j++) bi[j] = bias[c0 + j];
    #pragma unroll
    for (int i = 0; i < 8; i++) {
        int r = m0 + ty * 8 + i;
        if (r >= MP) continue;
        float* cp = C + (size_t)r * DM + c0;
        #pragma unroll
        for (int j = 0; j < 4; j++) {
            float2 f = unpack2(acc[i][j]);
            cp[j*2+0] = f.x + bi[j*2+0];
            cp[j*2+1] = f.y + bi[j*2+1];
        }
    }
}

// ---------------- batched scores GEMM: scores[b,h] = Qh @ Kh^T -------------
__global__ __launch_bounds__(256) void scores_gemm_kernel()
{
    const int z = blockIdx.z;
    const int b = z >> 3, h = z & 7;
    const float* A  = g_q + (size_t)b * PP * DM + h * DK;
    const float* Bm = g_k + (size_t)b * PP * DM + h * DK;
    float* C = g_scores + (size_t)z * P2;

    __shared__ __align__(16) float As[16][132];
    __shared__ __align__(16) float Bs[16][132];
    const int t  = threadIdx.x;
    const int m0 = blockIdx.y * 128;
    const int n0 = blockIdx.x * 128;
    const int lr = t >> 2;
    const int lc = (t & 3) << 2;
    const int ty = t >> 4, tx = t & 15;
    u64 acc[8][4];
    #pragma unroll
    for (int i = 0; i < 8; i++)
        #pragma unroll
        for (int j = 0; j < 4; j++) acc[i][j] = 0ull;

    for (int k0 = 0; k0 < DK; k0 += 16) {
        int ar0 = m0 + lr, ar1 = m0 + lr + 64;
        int br0 = n0 + lr, br1 = n0 + lr + 64;
        float4 a0 = make_float4(0.f,0.f,0.f,0.f), a1 = a0, b0 = a0, b1 = a0;
        if (ar0 < PP) a0 = *(const float4*)(A  + (size_t)ar0 * DM + k0 + lc);
        if (ar1 < PP) a1 = *(const float4*)(A  + (size_t)ar1 * DM + k0 + lc);
        if (br0 < PP) b0 = *(const float4*)(Bm + (size_t)br0 * DM + k0 + lc);
        if (br1 < PP) b1 = *(const float4*)(Bm + (size_t)br1 * DM + k0 + lc);
        if (k0) __syncthreads();
        As[lc+0][lr] = a0.x; As[lc+1][lr] = a0.y; As[lc+2][lr] = a0.z; As[lc+3][lr] = a0.w;
        As[lc+0][lr+64] = a1.x; As[lc+1][lr+64] = a1.y; As[lc+2][lr+64] = a1.z; As[lc+3][lr+64] = a1.w;
        Bs[lc+0][lr] = b0.x; Bs[lc+1][lr] = b0.y; Bs[lc+2][lr] = b0.z; Bs[lc+3][lr] = b0.w;
        Bs[lc+0][lr+64] = b1.x; Bs[lc+1][lr+64] = b1.y; Bs[lc+2][lr+64] = b1.z; Bs[lc+3][lr+64] = b1.w;
        __syncthreads();
        #pragma unroll
        for (int kk = 0; kk < 16; kk++) {
            float a[8];
            *(float4*)&a[0] = *(const float4*)&As[kk][ty*8];
            *(float4*)&a[4] = *(const float4*)&As[kk][ty*8+4];
            ulonglong2 B0 = *(const ulonglong2*)&Bs[kk][tx*8];
            ulonglong2 B1 = *(const ulonglong2*)&Bs[kk][tx*8+4];
            #pragma unroll
            for (int i = 0; i < 8; i++) {
                u64 aa = pack2(a[i], a[i]);
                acc[i][0] = ffma2(aa, B0.x, acc[i][0]);
                acc[i][1] = ffma2(aa, B0.y, acc[i][1]);
                acc[i][2] = ffma2(aa, B1.x, acc[i][2]);
                acc[i][3] = ffma2(aa, B1.y, acc[i][3]);
            }
        }
    }
    const int c0 = n0 + tx * 8;
    #pragma unroll
    for (int i = 0; i < 8; i++) {
        int r = m0 + ty * 8 + i;
        if (r >= PP) continue;
        float* cp = C + (size_t)r * PP;
        #pragma unroll
        for (int j = 0; j < 4; j++) {
            float2 f = unpack2(acc[i][j]);
            int c = c0 + j * 2;
            if (c     < PP) cp[c]     = f.x;
            if (c + 1 < PP) cp[c + 1] = f.y;
        }
    }
}

// ---------------- column argmax over p for each (bh, w) --------------------
__global__ __launch_bounds__(256) void argmax_kernel()
{
    const int w  = blockIdx.x * 256 + threadIdx.x;
    const int bh = blockIdx.y;
    if (w >= PP) return;
    const float* base = g_scores + (size_t)bh * P2 + w;
    float best = base[0];
    int   bi = 0;
    int p = 1;
    for (; p + 15 < PP; p += 16) {
        float v[16];
        #pragma unroll
        for (int u = 0; u < 16; u++) v[u] = base[(size_t)(p + u) * PP];
        #pragma unroll
        for (int u = 0; u < 16; u++)
            if (v[u] > best) { best = v[u]; bi = p + u; }
    }
    for (; p < PP; p++) {
        float v = base[(size_t)p * PP];
        if (v > best) { best = v; bi = p; }
    }
    g_idx[bh * PP + w] = bi;
}

// ---------------- gaussian modulation + scale + softmax (in-place) ---------
__global__ __launch_bounds__(256) void gauss_softmax_kernel()
{
    const int p  = blockIdx.x;
    const int bh = blockIdx.y;
    float* row = g_scores + ((size_t)bh * PP + p) * PP;
    const int* idxr = g_idx + bh * PP;
    const int t = threadIdx.x;
    const float ys0 = -1.0f + (2.0f / 29.0f) * (float)(p / SIDE);
    const float xs0 = -1.0f + (2.0f / 29.0f) * (float)(p % SIDE);

    __shared__ float sh[32];
    float v[4];
    float m = -3.0e38f;
    #pragma unroll
    for (int i = 0; i < 4; i++) {
        int w = t + i * 256;
        v[i] = -3.0e38f;
        if (w < PP) {
            int id = idxr[w];
            int iy = id / SIDE;
            float fy = (float)iy;
            float fx = (float)(id - iy * SIDE);
            float ddx = xs0 - fx;
            float ddy = ys0 - fy;
            float g = expf(-(ddx * ddx + ddy * ddy) * (1.0f / 50.0f));
            v[i] = g * row[w] * 0.125f;
            m = fmaxf(m, v[i]);
        }
    }
    #pragma unroll
    for (int off = 16; off; off >>= 1) m = fmaxf(m, __shfl_xor_sync(0xffffffffu, m, off));
    if ((t & 31) == 0) sh[t >> 5] = m;
    __syncthreads();
    if (t < 32) {
        float x = (t < 8) ? sh[t] : -3.0e38f;
        #pragma unroll
        for (int off = 4; off; off >>= 1) x = fmaxf(x, __shfl_xor_sync(0xffffffffu, x, off));
        if (t == 0) sh[0] = x;
    }
    __syncthreads();
    m = sh[0];
    __syncthreads();

    float e[4];
    float s = 0.f;
    #pragma unroll
    for (int i = 0; i < 4; i++) {
        int w = t + i * 256;
        e[i] = 0.f;
        if (w < PP) { e[i] = expf(v[i] - m); s += e[i]; }
    }
    #pragma unroll
    for (int off = 16; off; off >>= 1) s += __shfl_xor_sync(0xffffffffu, s, off);
    if ((t & 31) == 0) sh[t >> 5] = s;
    __syncthreads();
    if (t < 32) {
        float x = (t < 8) ? sh[t] : 0.f;
        #pragma unroll
        for (int off = 4; off; off >>= 1) x += __shfl_xor_sync(0xffffffffu, x, off);
        if (t == 0) sh[0] = x;
    }
    __syncthreads();
    float inv = 1.0f / sh[0];
    #pragma unroll
    for (int i = 0; i < 4; i++) {
        int w = t + i * 256;
        if (w < PP) row[w] = e[i] * inv;
    }
}

// ---------------- conv1 (8->32 ch, 3x3 SAME) + bias + relu -----------------
// block = (p, b). Thread: 4 oc-pairs (8 ch) x 4 CONTIGUOUS w, f32x2 packed.
__global__ __launch_bounds__(256) void conv1_kernel(
    const float* __restrict__ w1, const float* __restrict__ b1)
{
    const int p = blockIdx.x;
    const int b = blockIdx.y;
    // wsm[(ci*9 + dy*3 + dx)*16 + ocg*4 + op] = pack(w[oc0], w[oc0+1])
    __shared__ u64 wsm[8 * 9 * 16];
    for (int i = threadIdx.x; i < 8 * 9 * 16; i += 256) {
        int op  = i & 3;
        int ocg = (i >> 2) & 3;
        int rest = i >> 4;
        int ci  = rest / 9;
        int dydx = rest - ci * 9;
        int oc0 = ocg * 8 + op * 2;
        float wa = w1[(oc0 * 8 + ci) * 9 + dydx];
        float wb = w1[((oc0 + 1) * 8 + ci) * 9 + dydx];
        wsm[i] = pack2(wa, wb);
    }
    __syncthreads();

    const int ocg  = threadIdx.x >> 6;
    const int s    = threadIdx.x & 63;
    const float* inb = g_scores + (size_t)b * HH * P2;

    u64 bia[4];
    #pragma unroll
    for (int op = 0; op < 4; op++)
        bia[op] = pack2(b1[ocg * 8 + op * 2], b1[ocg * 8 + op * 2 + 1]);

    #pragma unroll 1
    for (int j = 0; j < 4; j++) {
        const int c  = s + 64 * j;         // chunk index, 225 active
        const bool active = (c < 225);
        const int w0 = c * 4;
        u64 acc[4][4];
        #pragma unroll
        for (int k = 0; k < 4; k++)
            #pragma unroll
            for (int op = 0; op < 4; op++) acc[k][op] = bia[op];

        #pragma unroll 1
        for (int ci = 0; ci < 8; ci++) {
            const float* rowbase = inb + (size_t)ci * P2;
            #pragma unroll
            for (int dy = 0; dy < 3; dy++) {
                int r = p + dy - 1;
                if (r < 0 || r >= PP) continue;
                const float* rowp = rowbase + (size_t)r * PP;
                float4 v = make_float4(0.f,0.f,0.f,0.f);
                float vm = 0.f, vp = 0.f;
                if (active) {
                    v = *(const float4*)(rowp + w0);
                    if (c > 0)   vm = rowp[w0 - 1];
                    if (c < 224) vp = rowp[w0 + 4];
                }
                u64 in2[6];
                in2[0] = pack2(vm, vm);  in2[1] = pack2(v.x, v.x);
                in2[2] = pack2(v.y, v.y); in2[3] = pack2(v.z, v.z);
                in2[4] = pack2(v.w, v.w); in2[5] = pack2(vp, vp);
                const u64* wb = &wsm[(ci * 9 + dy * 3) * 16 + ocg * 4];
                #pragma unroll
                for (int dx = 0; dx < 3; dx++) {
                    u64 wp0 = wb[dx * 16 + 0];
                    u64 wp1 = wb[dx * 16 + 1];
                    u64 wp2 = wb[dx * 16 + 2];
                    u64 wp3 = wb[dx * 16 + 3];
                    #pragma unroll
                    for (int k = 0; k < 4; k++) {
                        acc[k][0] = ffma2(in2[k + dx], wp0, acc[k][0]);
                        acc[k][1] = ffma2(in2[k + dx], wp1, acc[k][1]);
                        acc[k][2] = ffma2(in2[k + dx], wp2, acc[k][2]);
                        acc[k][3] = ffma2(in2[k + dx], wp3, acc[k][3]);
                    }
                }
            }
        }
        if (active) {
            size_t outb = (((size_t)b * C1 + ocg * 8) * PP + p) * (size_t)PP + w0;
            #pragma unroll
            for (int op = 0; op < 4; op++) {
                float2 f0 = unpack2(acc[0][op]);
                float2 f1 = unpack2(acc[1][op]);
                float2 f2 = unpack2(acc[2][op]);
                float2 f3 = unpack2(acc[3][op]);
                float4 oA = make_float4(fmaxf(f0.x,0.f), fmaxf(f1.x,0.f),
                                        fmaxf(f2.x,0.f), fmaxf(f3.x,0.f));
                float4 oB = make_float4(fmaxf(f0.y,0.f), fmaxf(f1.y,0.f),
                                        fmaxf(f2.y,0.f), fmaxf(f3.y,0.f));
                *(float4*)&g_c1[outb + (size_t)(op * 2 + 0) * P2] = oA;
                *(float4*)&g_c1[outb + (size_t)(op * 2 + 1) * P2] = oB;
            }
        }
    }
}

// ------- conv2 (32->8 ch) + bias + relu + value-dot + head-mean ------------
// block = (p, b); thread t owns 4 contiguous w (w0 = 4t), 225 active threads.
__global__ __launch_bounds__(256) void conv2_reduce_kernel(
    const float* __restrict__ w2, const float* __restrict__ b2,
    const float* __restrict__ value, float* __restrict__ out)
{
    const int p = blockIdx.x;
    const int b = blockIdx.y;
    __shared__ u64 wsm[32 * 9 * 4];
    for (int i = threadIdx.x; i < 32 * 9 * 4; i += 256) {
        int op = i & 3;
        int rest = i >> 2;
        int ci = rest / 9;
        int dydx = rest - ci * 9;
        int oc0 = op * 2;
        float wa = w2[(oc0 * 32 + ci) * 9 + dydx];
        float wb = w2[((oc0 + 1) * 32 + ci) * 9 + dydx];
        wsm[i] = pack2(wa, wb);
    }
    __syncthreads();

    const int t = threadIdx.x;
    const bool active = (t < 225);
    const int w0 = t * 4;
    const float* inb = g_c1 + (size_t)b * C1 * P2;

    u64 acc[4][4];
    #pragma unroll
    for (int k = 0; k < 4; k++)
        #pragma unroll
        for (int op = 0; op < 4; op++)
            acc[k][op] = pack2(b2[op * 2], b2[op * 2 + 1]);

    #pragma unroll 1
    for (int ci = 0; ci < C1; ci++) {
        const float* rowbase = inb + (size_t)ci * P2;
        #pragma unroll
        for (int dy = 0; dy < 3; dy++) {
            int r = p + dy - 1;
            if (r < 0 || r >= PP) continue;
            const float* rowp = rowbase + (size_t)r * PP;
            float4 v = make_float4(0.f,0.f,0.f,0.f);
            float vm = 0.f, vp = 0.f;
            if (active) {
                v = *(const float4*)(rowp + w0);
                if (t > 0)   vm = rowp[w0 - 1];
                if (t < 224) vp = rowp[w0 + 4];
            }
            u64 in2[6];
            in2[0] = pack2(vm, vm);  in2[1] = pack2(v.x, v.x);
            in2[2] = pack2(v.y, v.y); in2[3] = pack2(v.z, v.z);
            in2[4] = pack2(v.w, v.w); in2[5] = pack2(vp, vp);
            const u64* wb = &wsm[(ci * 9 + dy * 3) * 4];
            #pragma unroll
            for (int dx = 0; dx < 3; dx++) {
                u64 wp0 = wb[dx * 4 + 0];
                u64 wp1 = wb[dx * 4 + 1];
                u64 wp2 = wb[dx * 4 + 2];
                u64 wp3 = wb[dx * 4 + 3];
                #pragma unroll
                for (int k = 0; k < 4; k++) {
                    acc[k][0] = ffma2(in2[k + dx], wp0, acc[k][0]);
                    acc[k][1] = ffma2(in2[k + dx], wp1, acc[k][1]);
                    acc[k][2] = ffma2(in2[k + dx], wp2, acc[k][2]);
                    acc[k][3] = ffma2(in2[k + dx], wp3, acc[k][3]);
                }
            }
        }
    }

    float part = 0.f;
    if (active) {
        float4 vv = *(const float4*)(value + b * PP + w0);
        float val[4] = {vv.x, vv.y, vv.z, vv.w};
        #pragma unroll
        for (int k = 0; k < 4; k++) {
            float s = 0.f;
            #pragma unroll
            for (int op = 0; op < 4; op++) {
                float2 f = unpack2(acc[k][op]);
                s += fmaxf(f.x, 0.f) + fmaxf(f.y, 0.f);
            }
            part += s * val[k];
        }
    }
    __shared__ float sh[32];
    #pragma unroll
    for (int off = 16; off; off >>= 1) part += __shfl_xor_sync(0xffffffffu, part, off);
    if ((t & 31) == 0) sh[t >> 5] = part;
    __syncthreads();
    if (t < 32) {
        float x = (t < 8) ? sh[t] : 0.f;
        #pragma unroll
        for (int off = 4; off; off >>= 1) x += __shfl_xor_sync(0xffffffffu, x, off);
        if (t == 0) out[b * PP + p] = x * 0.125f;
    }
}

// ---------------------------------------------------------------------------
extern "C" void kernel_launch(void* const* d_in, const int* in_sizes, int n_in,
                              void* d_out, int out_size)
{
    const float* query = (const float*)d_in[0];
    const float* key_t = (const float*)d_in[1];
    const float* value = (const float*)d_in[2];
    const float* Wq    = (const float*)d_in[3];
    const float* bq    = (const float*)d_in[4];
    const float* Wk    = (const float*)d_in[5];
    const float* bk    = (const float*)d_in[6];
    const float* c1w   = (const float*)d_in[7];
    const float* c1b   = (const float*)d_in[8];
    const float* c2w   = (const float*)d_in[9];
    const float* c2b   = (const float*)d_in[10];
    float* out = (float*)d_out;
    (void)in_sizes; (void)n_in; (void)out_size;

    proj_gemm_kernel<<<dim3(4, 29), 256>>>(query, Wq, bq, 0);
    proj_gemm_kernel<<<dim3(4, 29), 256>>>(key_t, Wk, bk, 1);
    scores_gemm_kernel<<<dim3(8, 8, 32), 256>>>();
    argmax_kernel<<<dim3(4, 32), 256>>>();
    gauss_softmax_kernel<<<dim3(900, 32), 256>>>();
    conv1_kernel<<<dim3(900, 4), 256>>>(c1w, c1b);
    conv2_reduce_kernel<<<dim3(900, 4), 256>>>(c2w, c2b, value, out);
}